// round 14
// baseline (speedup 1.0000x reference)
#include <cuda_runtime.h>
#include <math.h>

// ---------------------------------------------------------------------------
// Problem constants
// ---------------------------------------------------------------------------
#define NB     4096
// conv1: 1 -> 32 ch, 28x28, pad 2, pool -> 14x14  (tensor-core implicit GEMM)
// conv2: 32 -> 64 ch, 14x14, pad 2, pool -> 7x7   (tensor-core implicit GEMM)
// fc1:   3136 -> 128, relu (tensor-core GEMM) ; fc2: 128 -> 10

// conv1 output: padded spatial grid 18x18 (coords -2..15), channel-minor,
// position stride 36 floats (32 ci + 4 pad) -> conflict-free A fragments.
#define P1POS 324            // 18*18
#define P1POS_PAD 336        // pad so shifted A-fragment rows stay in-bounds
#define P1STRIDE 36
#define P1FL (P1POS_PAD * P1STRIDE)   // 12096 floats per image

// ---------------------------------------------------------------------------
// helpers
// ---------------------------------------------------------------------------
__device__ __forceinline__ unsigned smem_u32(const void* p) {
    unsigned a;
    asm("{ .reg .u64 t; cvta.to.shared.u64 t, %1; cvt.u32.u64 %0, t; }"
        : "=r"(a) : "l"(p));
    return a;
}
__device__ __forceinline__ void cpa16(unsigned s, const void* g) {
    asm volatile("cp.async.cg.shared.global [%0], [%1], 16;" :: "r"(s), "l"(g));
}
#define CP_COMMIT() asm volatile("cp.async.commit_group;")
#define CP_WAIT0()  asm volatile("cp.async.wait_group 0;" ::: "memory")
#define CP_WAIT1()  asm volatile("cp.async.wait_group 1;" ::: "memory")

__device__ __forceinline__ float to_tf32(float x) {
    unsigned r;
    asm("cvt.rna.tf32.f32 %0, %1;" : "=r"(r) : "f"(x));
    return __uint_as_float(r);
}

__device__ __forceinline__ void mma8(float c[4],
                                     unsigned a0, unsigned a1, unsigned a2, unsigned a3,
                                     unsigned b0, unsigned b1) {
    asm volatile("mma.sync.aligned.m16n8k8.row.col.f32.tf32.tf32.f32 "
                 "{%0,%1,%2,%3}, {%4,%5,%6,%7}, {%8,%9}, {%0,%1,%2,%3};"
                 : "+f"(c[0]), "+f"(c[1]), "+f"(c[2]), "+f"(c[3])
                 : "r"(a0), "r"(a1), "r"(a2), "r"(a3), "r"(b0), "r"(b1));
}

// ---------------------------------------------------------------------------
// Device scratch
// ---------------------------------------------------------------------------
__device__ float g_K1[32 * 25];                  // [co][tap]
__device__ float g_K1p[1024];                    // packed tf32 conv1 B frags [ks][nt][lane][2]
__device__ float g_K2[32 * 64 * 25];             // dense [ci][co][tap]
__device__ float g_K2p[25 * 2048];               // packed tf32 conv2 B frags [tap][ks][nt][lane][2]
__device__ float g_pool1[NB * P1FL];             // conv1 out, tf32, [pos][ci]
__device__ float g_pool2[NB * 64 * 7 * 7];       // [b][pos*64+co], tf32
__device__ float g_fc1o[NB * 128];
__device__ float g_fc1wp[392 * 16 * 64];         // packed tf32 fc1 B frags [ks][nt][lane][2]

// ---------------------------------------------------------------------------
// Kernel 1: build dense DCLS kernels
// ---------------------------------------------------------------------------
__global__ void build_kernels_k(const float* __restrict__ w1,
                                const float* __restrict__ p1,
                                const float* __restrict__ w2,
                                const float* __restrict__ p2) {
    int t = blockIdx.x * blockDim.x + threadIdx.x;
    if (t >= 32 + 64 * 32) return;

    float acc[36];
#pragma unroll
    for (int i = 0; i < 36; i++) acc[i] = 0.f;

    if (t < 32) {
        int co = t;
        for (int kc = 0; kc < 16; kc++) {
            float wv = w1[co * 16 + kc];
            float pa = p1[0 * 32 * 16 + co * 16 + kc];
            float pb = p1[1 * 32 * 16 + co * 16 + kc];
            pa = fminf(fmaxf(pa, -2.f), 2.f) + 2.f;
            pb = fminf(fmaxf(pb, -2.f), 2.f) + 2.f;
            int   i1 = (int)floorf(pa), i2 = (int)floorf(pb);
            float r1 = pa - (float)i1,  r2 = pb - (float)i2;
            acc[i1 * 6 + i2]           += wv * (1.f - r1) * (1.f - r2);
            acc[(i1 + 1) * 6 + i2]     += wv * r1 * (1.f - r2);
            acc[i1 * 6 + i2 + 1]       += wv * (1.f - r1) * r2;
            acc[(i1 + 1) * 6 + i2 + 1] += wv * r1 * r2;
        }
        for (int ky = 0; ky < 5; ky++)
            for (int kx = 0; kx < 5; kx++)
                g_K1[co * 25 + ky * 5 + kx] = acc[ky * 6 + kx];
    } else {
        int idx = t - 32;
        int co = idx / 32, ci = idx % 32;
        for (int kc = 0; kc < 32; kc++) {
            float wv = w2[(co * 32 + ci) * 32 + kc];
            float pa = p2[0 * 64 * 32 * 32 + (co * 32 + ci) * 32 + kc];
            float pb = p2[1 * 64 * 32 * 32 + (co * 32 + ci) * 32 + kc];
            pa = fminf(fmaxf(pa, -2.f), 2.f) + 2.f;
            pb = fminf(fmaxf(pb, -2.f), 2.f) + 2.f;
            int   i1 = (int)floorf(pa), i2 = (int)floorf(pb);
            float r1 = pa - (float)i1,  r2 = pb - (float)i2;
            acc[i1 * 6 + i2]           += wv * (1.f - r1) * (1.f - r2);
            acc[(i1 + 1) * 6 + i2]     += wv * r1 * (1.f - r2);
            acc[i1 * 6 + i2 + 1]       += wv * (1.f - r1) * r2;
            acc[(i1 + 1) * 6 + i2 + 1] += wv * r1 * r2;
        }
        for (int ky = 0; ky < 5; ky++)
            for (int kx = 0; kx < 5; kx++)
                g_K2[(ci * 64 + co) * 25 + ky * 5 + kx] = acc[ky * 6 + kx];
    }
}

// ---------------------------------------------------------------------------
// Kernel 1b: repack conv2 + conv1 weights into per-fragment tf32 layouts.
// conv2: packed idx = ((tap*4 + ks)*8 + nt)*64 + lane*2 + h
// conv1: packed idx = ((ks*4 + nt)*32 + lane)*2 + h over taps (K padded to 32)
// Fragment map (validated): k = ks*8 + (lane&3) + 4h, n = nt*8 + (lane>>2)
// ---------------------------------------------------------------------------
__global__ void repack_w_k() {
    int idx = blockIdx.x * 256 + threadIdx.x;
    if (idx < 25 * 2048) {
        int tap = idx / 2048, r = idx % 2048;
        int ks = r >> 9;
        int r2 = r & 511;
        int nt = r2 >> 6;
        int r3 = r2 & 63;
        int lane = r3 >> 1, h = r3 & 1;
        int k = ks * 8 + (lane & 3) + 4 * h;
        int n = nt * 8 + (lane >> 2);
        g_K2p[idx] = to_tf32(g_K2[(k * 64 + n) * 25 + tap]);
    } else if (idx < 25 * 2048 + 1024) {
        int q = idx - 25 * 2048;
        int ks = q >> 8;
        int nt = (q >> 6) & 3;
        int r3 = q & 63;
        int lane = r3 >> 1, h = r3 & 1;
        int k = ks * 8 + (lane & 3) + 4 * h;   // tap index (0..31, 25..31 pad)
        int n = nt * 8 + (lane >> 2);          // co
        g_K1p[q] = (k < 25) ? to_tf32(g_K1[n * 25 + k]) : 0.f;
    }
}

// ---------------------------------------------------------------------------
// Kernel 2: pack fc1_w into fragment-ordered tf32 layout.
// ---------------------------------------------------------------------------
__global__ void pack_fc1w_k(const float* __restrict__ w) {
    int idx = blockIdx.x * 256 + threadIdx.x;
    if (idx >= 392 * 1024) return;
    int ks = idx >> 10;
    int r  = idx & 1023;
    int nt = r >> 6;
    int r2 = r & 63;
    int lane = r2 >> 1, h = r2 & 1;
    int k = ks * 8 + (lane & 3) + 4 * h;
    int n = nt * 8 + (lane >> 2);
    int pos = k >> 6, co = k & 63;
    g_fc1wp[idx] = to_tf32(w[n * 3136 + co * 49 + pos]);
}

// ---------------------------------------------------------------------------
// Kernel 3: conv1 as implicit GEMM on mma.sync tf32.
// A[m][k] = xs[m + shift(k)], m = y*32+x in the padded 32x32 image,
// shift(tap) = ky*32+kx. M=896 (junk cols discarded at pooling), K=25->32,
// N=32. B preloaded to registers. Two row-halves: MMA -> smem stage ->
// 2x2 pool + bias + relu -> padded [pos][ci] tf32 output. 2 CTAs/SM.
// ---------------------------------------------------------------------------
#define C1M_THREADS 256
#define C1M_XS 1056
#define C1M_STAG_STRIDE 34
#define C1M_SMEM_FL (C1M_XS + 448 * C1M_STAG_STRIDE)   // 1056 + 15232 = 16288

__global__ __launch_bounds__(C1M_THREADS, 2) void conv1_mma_k(const float* __restrict__ x,
                                                              const float* __restrict__ b1) {
    extern __shared__ float c1sm[];
    float* xs   = c1sm;              // padded image, linear 32x32 (+ zero tail)
    float* stag = c1sm + C1M_XS;     // [448][34] C staging per half

    int b = blockIdx.x;
    int t = threadIdx.x;
    int warp = t >> 5, lane = t & 31;
    int g = lane >> 2, tig = lane & 3;

    const float* xp = x + b * 784;
    for (int i = t; i < C1M_XS; i += C1M_THREADS) {
        float v = 0.f;
        if (i < 1024) {
            int r = (i >> 5) - 2, c = (i & 31) - 2;
            if (r >= 0 && r < 28 && c >= 0 && c < 28) v = xp[r * 28 + c];
        }
        xs[i] = v;
    }

    float* outp = g_pool1 + (size_t)b * P1FL;
    // zero border cells: 140 pos x 32 ci (rows 0,1,16,17; cols 0,1,16,17; tail)
    for (int i = t; i < 140 * 32; i += C1M_THREADS) {
        int p = i >> 5, ci = i & 31;
        int pos;
        if (p < 72) {
            int r = p / 18;
            int pr = (r < 2) ? r : 14 + r;
            pos = pr * 18 + (p - r * 18);
        } else if (p < 128) {
            int q = p - 72;
            int pr = 2 + (q >> 2);
            int c4 = q & 3;
            int pc = (c4 < 2) ? c4 : 14 + c4;
            pos = pr * 18 + pc;
        } else {
            pos = 324 + (p - 128);
        }
        outp[pos * P1STRIDE + ci] = 0.f;
    }

    // B fragments -> registers (validated col-major frag layout)
    float2 bf[4][4];
#pragma unroll
    for (int ks = 0; ks < 4; ks++)
#pragma unroll
        for (int nt = 0; nt < 4; nt++)
            bf[ks][nt] = *(const float2*)(g_K1p + ((ks * 4 + nt) * 32 + lane) * 2);

    // per-thread shift table: k = ks*8 + tig + 4h -> shift = (k/5)*32 + k%5
    int sh[4][2];
#pragma unroll
    for (int ks = 0; ks < 4; ks++)
#pragma unroll
        for (int h = 0; h < 2; h++) {
            int k = ks * 8 + tig + 4 * h;
            sh[ks][h] = (k < 25) ? (k / 5) * 32 + (k % 5) : 0;
        }

    __syncthreads();

#pragma unroll 1
    for (int half = 0; half < 2; half++) {
        int mhb = half * 448;

        // MMA phase: 28 m-tiles of 16 in this half, warps round-robin
#pragma unroll 1
        for (int mt = warp; mt < 28; mt += 8) {
            int m0 = mhb + mt * 16 + g;
            float c[4][4];
#pragma unroll
            for (int i = 0; i < 4; i++)
#pragma unroll
                for (int j = 0; j < 4; j++) c[i][j] = 0.f;

#pragma unroll
            for (int ks = 0; ks < 4; ks++) {
                unsigned a0 = __float_as_uint(xs[m0 + sh[ks][0]]);
                unsigned a1 = __float_as_uint(xs[m0 + 8 + sh[ks][0]]);
                unsigned a2 = __float_as_uint(xs[m0 + sh[ks][1]]);
                unsigned a3 = __float_as_uint(xs[m0 + 8 + sh[ks][1]]);
#pragma unroll
                for (int nt = 0; nt < 4; nt++)
                    mma8(c[nt], a0, a1, a2, a3,
                         __float_as_uint(bf[ks][nt].x), __float_as_uint(bf[ks][nt].y));
            }
            // stage C tile rows (half-local m)
#pragma unroll
            for (int nt = 0; nt < 4; nt++) {
                float* s = stag + (mt * 16 + g) * C1M_STAG_STRIDE + nt * 8 + 2 * tig;
                *(float2*)s = make_float2(c[nt][0], c[nt][1]);
                *(float2*)(s + 8 * C1M_STAG_STRIDE) = make_float2(c[nt][2], c[nt][3]);
            }
        }
        __syncthreads();

        // pooling epilogue for this half: yp_local 0..6, xq 0..13, ci 0..31
        for (int o = t; o < 7 * 14 * 32; o += C1M_THREADS) {
            int ci = o & 31, pq = o >> 5;
            int ypl = pq / 14, xq = pq % 14;
            int lm = (2 * ypl) * 32 + 2 * xq;
            float v0 = stag[lm * C1M_STAG_STRIDE + ci];
            float v1 = stag[(lm + 1) * C1M_STAG_STRIDE + ci];
            float v2 = stag[(lm + 32) * C1M_STAG_STRIDE + ci];
            float v3 = stag[(lm + 33) * C1M_STAG_STRIDE + ci];
            float mx = fmaxf(fmaxf(v0, v1), fmaxf(v2, v3)) + b1[ci];
            int yp = half * 7 + ypl;
            int pos = (yp + 2) * 18 + (xq + 2);
            outp[pos * P1STRIDE + ci] = to_tf32(fmaxf(mx, 0.f));
        }
        __syncthreads();   // stag reuse in next half
    }
}

// ---------------------------------------------------------------------------
// Kernel 4: conv2 as implicit GEMM on mma.sync tf32 (R10-proven).
// ---------------------------------------------------------------------------
#define C2M_THREADS 256
#define C2M_CHUNK_FL (5 * 2048)                      // 5 taps of packed B
#define C2M_SMEM_FL (P1FL + C2M_CHUNK_FL)            // 12096 + 10240 = 22336
#define C2M_STAG_STRIDE 66                           // staging 256*66 = 16896 <= 22336

__global__ __launch_bounds__(C2M_THREADS, 2) void conv2_mma_k(const float* __restrict__ b2) {
    extern __shared__ float sm[];
    float* in_lin = sm;                          // [336][36]
    float* bbuf   = sm + P1FL;                   // single 5-tap weight chunk

    int b = blockIdx.x;
    int t = threadIdx.x;
    int warp = t >> 5, lane = t & 31;
    int g = lane >> 2, tig = lane & 3;

    unsigned in_a = smem_u32(in_lin);
    unsigned b_a  = smem_u32(bbuf);

    // group 0: input image + weight chunk 0
    {
        const char* ip = (const char*)(g_pool1 + (size_t)b * P1FL);
        for (int i = t; i < P1FL / 4; i += C2M_THREADS) cpa16(in_a + i * 16, ip + i * 16);
        const char* w0 = (const char*)g_K2p;
        for (int i = t; i < C2M_CHUNK_FL / 4; i += C2M_THREADS) cpa16(b_a + i * 16, w0 + i * 16);
    }
    CP_COMMIT();

    float c[16][4];
#pragma unroll
    for (int i = 0; i < 16; i++)
#pragma unroll
        for (int j = 0; j < 4; j++) c[i][j] = 0.f;

    for (int ch = 0; ch < 5; ch++) {           // ch == ky (5 taps per chunk)
        CP_WAIT0();
        __syncthreads();

#pragma unroll 1
        for (int t5 = 0; t5 < 5; t5++) {       // kx
            int shift = ch * 18 + t5;          // ky*18 + kx
            const float* bt = bbuf + t5 * 2048;
            const unsigned* au =
                (const unsigned*)(in_lin + (warp * 32 + g + shift) * P1STRIDE + tig);

#pragma unroll
            for (int ksI = 0; ksI < 4; ksI++) {
                int kb = ksI * 8;
                unsigned a00 = au[kb],                 a01 = au[8 * P1STRIDE + kb];
                unsigned a02 = au[kb + 4],             a03 = au[8 * P1STRIDE + kb + 4];
                unsigned a10 = au[16 * P1STRIDE + kb], a11 = au[24 * P1STRIDE + kb];
                unsigned a12 = au[16 * P1STRIDE + kb + 4], a13 = au[24 * P1STRIDE + kb + 4];

                const float* bks = bt + ksI * 512 + lane * 2;
#pragma unroll
                for (int nt = 0; nt < 8; nt++) {
                    float2 bv = *(const float2*)(bks + nt * 64);
                    unsigned b0 = __float_as_uint(bv.x);
                    unsigned b1 = __float_as_uint(bv.y);
                    mma8(c[nt],     a00, a01, a02, a03, b0, b1);
                    mma8(c[8 + nt], a10, a11, a12, a13, b0, b1);
                }
            }
        }
        __syncthreads();                       // chunk consumed
        if (ch + 1 < 5) {
            const char* wn = (const char*)(g_K2p + (ch + 1) * C2M_CHUNK_FL);
            for (int i = t; i < C2M_CHUNK_FL / 4; i += C2M_THREADS)
                cpa16(b_a + i * 16, wn + i * 16);
            CP_COMMIT();
        }
    }

    // ---- epilogue: stage C over the dead input buffer, pool, store ----
    float* stag = sm;                          // [m(0..255)][co] stride 66

#pragma unroll
    for (int mt = 0; mt < 2; mt++) {
#pragma unroll
        for (int nt = 0; nt < 8; nt++) {
            float* s = stag + (warp * 32 + mt * 16 + g) * C2M_STAG_STRIDE + nt * 8 + 2 * tig;
            *(float2*)s = make_float2(c[mt * 8 + nt][0], c[mt * 8 + nt][1]);
            *(float2*)(s + 8 * C2M_STAG_STRIDE) = make_float2(c[mt * 8 + nt][2], c[mt * 8 + nt][3]);
        }
    }
    __syncthreads();

    for (int o = t; o < 3136; o += C2M_THREADS) {
        int pos = o >> 6, co = o & 63;
        int yp = pos / 7, xp = pos % 7;
        int m00 = yp * 36 + xp * 2;            // (2yp)*18 + 2xp
        float v0 = stag[m00 * C2M_STAG_STRIDE + co];
        float v1 = stag[(m00 + 1) * C2M_STAG_STRIDE + co];
        float v2 = stag[(m00 + 18) * C2M_STAG_STRIDE + co];
        float v3 = stag[(m00 + 19) * C2M_STAG_STRIDE + co];
        float mx = fmaxf(fmaxf(v0, v1), fmaxf(v2, v3)) + b2[co];
        // tf32-round here: fc1's A operand comes straight from this buffer
        g_pool2[(size_t)b * 3136 + pos * 64 + co] = to_tf32(fmaxf(mx, 0.f));
    }
}

// ---------------------------------------------------------------------------
// Kernel 5: fc1 as tf32 MMA GEMM, BK=64 (R12-proven).
// ---------------------------------------------------------------------------
#define F1_THREADS 256
#define F1_A_FL (32 * 68)       // 2176 floats per A buffer
#define F1_B_FL 8192            // 8 ksteps x 1024 floats per B buffer
#define F1_SMEM_FL (2 * F1_A_FL + 2 * F1_B_FL)   // 20736 floats = 82944 B

__global__ __launch_bounds__(F1_THREADS, 1) void fc1_mma_k(const float* __restrict__ fc1_b) {
    extern __shared__ float fsm[];
    float* Abuf[2] = { fsm, fsm + F1_A_FL };
    float* Bbuf[2] = { fsm + 2 * F1_A_FL, fsm + 2 * F1_A_FL + F1_B_FL };

    int blk = blockIdx.x;               // 0..127, 32 rows each
    int t = threadIdx.x;
    int warp = t >> 5, lane = t & 31;
    int g = lane >> 2, tig = lane & 3;
    int mw = warp & 1;                  // 0..1
    int nw = warp >> 1;                 // 0..3

    unsigned as_a[2] = { smem_u32(Abuf[0]), smem_u32(Abuf[1]) };
    unsigned bs_a[2] = { smem_u32(Bbuf[0]), smem_u32(Bbuf[1]) };

    const float* Ag = g_pool2 + (size_t)blk * 32 * 3136;

    // chunk 0: A (512 cpa16) + B (2048 cpa16)
#pragma unroll
    for (int l = 0; l < 2; l++) {
        int i = t + l * F1_THREADS;               // 0..511
        int row = i >> 4, q = i & 15;
        cpa16(as_a[0] + (row * 68 + q * 4) * 4, Ag + row * 3136 + q * 4);
    }
    for (int i = t; i < 2048; i += F1_THREADS)
        cpa16(bs_a[0] + i * 16, g_fc1wp + i * 4);
    CP_COMMIT();

    float c[4][4];
#pragma unroll
    for (int i = 0; i < 4; i++)
#pragma unroll
        for (int j = 0; j < 4; j++) c[i][j] = 0.f;

    for (int ch = 0; ch < 49; ch++) {
        if (ch + 1 < 49) {
            int nb = (ch + 1) & 1;
#pragma unroll
            for (int l = 0; l < 2; l++) {
                int i = t + l * F1_THREADS;
                int row = i >> 4, q = i & 15;
                cpa16(as_a[nb] + (row * 68 + q * 4) * 4,
                      Ag + row * 3136 + (ch + 1) * 64 + q * 4);
            }
            const float* bsrc = g_fc1wp + (ch + 1) * F1_B_FL;
            for (int i = t; i < 2048; i += F1_THREADS)
                cpa16(bs_a[nb] + i * 16, bsrc + i * 4);
            CP_COMMIT();
            CP_WAIT1();
        } else {
            CP_WAIT0();
        }
        __syncthreads();

        const float* A_ = Abuf[ch & 1];
        const float* B_ = Bbuf[ch & 1];
#pragma unroll
        for (int ks = 0; ks < 8; ks++) {
            const unsigned* au = (const unsigned*)(A_ + (mw * 16 + g) * 68 + ks * 8 + tig);
            unsigned a0 = au[0], a1 = au[8 * 68], a2 = au[4], a3 = au[8 * 68 + 4];
            const float* bp = B_ + (ks * 16 + nw * 4) * 64 + lane * 2;
#pragma unroll
            for (int nt = 0; nt < 4; nt++) {
                float2 bv = *(const float2*)(bp + nt * 64);
                mma8(c[nt], a0, a1, a2, a3,
                     __float_as_uint(bv.x), __float_as_uint(bv.y));
            }
        }
        __syncthreads();   // buffer reuse safety before next prefetch
    }

    // epilogue: bias + relu, direct store
    int m0 = blk * 32 + mw * 16;
#pragma unroll
    for (int nt = 0; nt < 4; nt++) {
        int col = nw * 32 + nt * 8 + 2 * tig;
        float2 bb = *(const float2*)&fc1_b[col];
        float* o0 = g_fc1o + (m0 + g) * 128 + col;
        float* o1 = g_fc1o + (m0 + g + 8) * 128 + col;
        *(float2*)o0 = make_float2(fmaxf(c[nt][0] + bb.x, 0.f),
                                   fmaxf(c[nt][1] + bb.y, 0.f));
        *(float2*)o1 = make_float2(fmaxf(c[nt][2] + bb.x, 0.f),
                                   fmaxf(c[nt][3] + bb.y, 0.f));
    }
}

// ---------------------------------------------------------------------------
// Kernel 6: fc2  out[4096,10] = fc1o[4096,128] @ fc2_w[10,128]^T + b
// ---------------------------------------------------------------------------
__global__ __launch_bounds__(256) void fc2_k(const float* __restrict__ fc2_w,
                                             const float* __restrict__ fc2_b,
                                             float* __restrict__ out) {
    int idx = blockIdx.x * blockDim.x + threadIdx.x;
    if (idx >= NB * 10) return;
    int m = idx / 10, n = idx % 10;
    const float4* h = (const float4*)(g_fc1o + m * 128);
    const float4* w = (const float4*)(fc2_w + n * 128);
    float s = 0.f;
#pragma unroll
    for (int i = 0; i < 32; i++) {
        float4 a = h[i], bb = w[i];
        s += a.x * bb.x + a.y * bb.y + a.z * bb.z + a.w * bb.w;
    }
    out[idx] = s + fc2_b[n];
}

// ---------------------------------------------------------------------------
// Launch
// ---------------------------------------------------------------------------
extern "C" void kernel_launch(void* const* d_in, const int* in_sizes, int n_in,
                              void* d_out, int out_size) {
    const float* x     = (const float*)d_in[0];
    const float* w1    = (const float*)d_in[1];
    const float* p1    = (const float*)d_in[2];
    const float* b1    = (const float*)d_in[3];
    const float* w2    = (const float*)d_in[4];
    const float* p2    = (const float*)d_in[5];
    const float* b2    = (const float*)d_in[6];
    const float* fc1w  = (const float*)d_in[7];
    const float* fc1b  = (const float*)d_in[8];
    const float* fc2w  = (const float*)d_in[9];
    const float* fc2b  = (const float*)d_in[10];
    float* out = (float*)d_out;

    cudaFuncSetAttribute(conv1_mma_k, cudaFuncAttributeMaxDynamicSharedMemorySize,
                         C1M_SMEM_FL * 4);
    cudaFuncSetAttribute(conv2_mma_k, cudaFuncAttributeMaxDynamicSharedMemorySize,
                         C2M_SMEM_FL * 4);
    cudaFuncSetAttribute(fc1_mma_k, cudaFuncAttributeMaxDynamicSharedMemorySize,
                         F1_SMEM_FL * 4);

    build_kernels_k<<<(32 + 64 * 32 + 127) / 128, 128>>>(w1, p1, w2, p2);
    repack_w_k<<<(25 * 2048 + 1024 + 255) / 256, 256>>>();
    pack_fc1w_k<<<(392 * 1024 + 255) / 256, 256>>>(fc1w);
    conv1_mma_k<<<NB, C1M_THREADS, C1M_SMEM_FL * 4>>>(x, b1);
    conv2_mma_k<<<NB, C2M_THREADS, C2M_SMEM_FL * 4>>>(b2);
    fc1_mma_k<<<NB / 32, F1_THREADS, F1_SMEM_FL * 4>>>(fc1b);
    fc2_k<<<(NB * 10 + 255) / 256, 256>>>(fc2w, fc2b, out);
}

// round 15
// speedup vs baseline: 1.0644x; 1.0644x over previous
#include <cuda_runtime.h>
#include <math.h>

// ---------------------------------------------------------------------------
// Problem constants
// ---------------------------------------------------------------------------
#define NB     4096
// conv1+conv2 FUSED: 1->32 conv/pool in smem, then 32->64 conv/pool (MMA)
// fc1: 3136 -> 128, relu (tensor-core GEMM) ; fc2: 128 -> 10

// conv1 output (now smem-resident): padded 18x18 grid, channel-minor,
// position stride 36 floats -> conflict-free A fragments for conv2.
#define P1STRIDE 36
#define P1FL (336 * P1STRIDE)        // 12096 floats

// ---------------------------------------------------------------------------
// helpers
// ---------------------------------------------------------------------------
__device__ __forceinline__ unsigned smem_u32(const void* p) {
    unsigned a;
    asm("{ .reg .u64 t; cvta.to.shared.u64 t, %1; cvt.u32.u64 %0, t; }"
        : "=r"(a) : "l"(p));
    return a;
}
__device__ __forceinline__ void cpa16(unsigned s, const void* g) {
    asm volatile("cp.async.cg.shared.global [%0], [%1], 16;" :: "r"(s), "l"(g));
}
#define CP_COMMIT() asm volatile("cp.async.commit_group;")
#define CP_WAIT0()  asm volatile("cp.async.wait_group 0;" ::: "memory")
#define CP_WAIT1()  asm volatile("cp.async.wait_group 1;" ::: "memory")

__device__ __forceinline__ float to_tf32(float x) {
    unsigned r;
    asm("cvt.rna.tf32.f32 %0, %1;" : "=r"(r) : "f"(x));
    return __uint_as_float(r);
}

__device__ __forceinline__ void mma8(float c[4],
                                     unsigned a0, unsigned a1, unsigned a2, unsigned a3,
                                     unsigned b0, unsigned b1) {
    asm volatile("mma.sync.aligned.m16n8k8.row.col.f32.tf32.tf32.f32 "
                 "{%0,%1,%2,%3}, {%4,%5,%6,%7}, {%8,%9}, {%0,%1,%2,%3};"
                 : "+f"(c[0]), "+f"(c[1]), "+f"(c[2]), "+f"(c[3])
                 : "r"(a0), "r"(a1), "r"(a2), "r"(a3), "r"(b0), "r"(b1));
}

// ---------------------------------------------------------------------------
// Device scratch
// ---------------------------------------------------------------------------
__device__ float g_K1[32 * 25];                  // [co][tap]
__device__ float g_K1p[1024];                    // packed tf32 conv1 B frags
__device__ float g_K2[32 * 64 * 25];             // dense [ci][co][tap]
__device__ float g_K2p[25 * 2048];               // packed tf32 conv2 B frags
__device__ float g_pool2[NB * 64 * 7 * 7];       // [b][pos*64+co], tf32
__device__ float g_fc1o[NB * 128];
__device__ float g_fc1wp[392 * 16 * 64];         // packed tf32 fc1 B frags

// ---------------------------------------------------------------------------
// Kernel 1: build dense DCLS kernels
// ---------------------------------------------------------------------------
__global__ void build_kernels_k(const float* __restrict__ w1,
                                const float* __restrict__ p1,
                                const float* __restrict__ w2,
                                const float* __restrict__ p2) {
    int t = blockIdx.x * blockDim.x + threadIdx.x;
    if (t >= 32 + 64 * 32) return;

    float acc[36];
#pragma unroll
    for (int i = 0; i < 36; i++) acc[i] = 0.f;

    if (t < 32) {
        int co = t;
        for (int kc = 0; kc < 16; kc++) {
            float wv = w1[co * 16 + kc];
            float pa = p1[0 * 32 * 16 + co * 16 + kc];
            float pb = p1[1 * 32 * 16 + co * 16 + kc];
            pa = fminf(fmaxf(pa, -2.f), 2.f) + 2.f;
            pb = fminf(fmaxf(pb, -2.f), 2.f) + 2.f;
            int   i1 = (int)floorf(pa), i2 = (int)floorf(pb);
            float r1 = pa - (float)i1,  r2 = pb - (float)i2;
            acc[i1 * 6 + i2]           += wv * (1.f - r1) * (1.f - r2);
            acc[(i1 + 1) * 6 + i2]     += wv * r1 * (1.f - r2);
            acc[i1 * 6 + i2 + 1]       += wv * (1.f - r1) * r2;
            acc[(i1 + 1) * 6 + i2 + 1] += wv * r1 * r2;
        }
        for (int ky = 0; ky < 5; ky++)
            for (int kx = 0; kx < 5; kx++)
                g_K1[co * 25 + ky * 5 + kx] = acc[ky * 6 + kx];
    } else {
        int idx = t - 32;
        int co = idx / 32, ci = idx % 32;
        for (int kc = 0; kc < 32; kc++) {
            float wv = w2[(co * 32 + ci) * 32 + kc];
            float pa = p2[0 * 64 * 32 * 32 + (co * 32 + ci) * 32 + kc];
            float pb = p2[1 * 64 * 32 * 32 + (co * 32 + ci) * 32 + kc];
            pa = fminf(fmaxf(pa, -2.f), 2.f) + 2.f;
            pb = fminf(fmaxf(pb, -2.f), 2.f) + 2.f;
            int   i1 = (int)floorf(pa), i2 = (int)floorf(pb);
            float r1 = pa - (float)i1,  r2 = pb - (float)i2;
            acc[i1 * 6 + i2]           += wv * (1.f - r1) * (1.f - r2);
            acc[(i1 + 1) * 6 + i2]     += wv * r1 * (1.f - r2);
            acc[i1 * 6 + i2 + 1]       += wv * (1.f - r1) * r2;
            acc[(i1 + 1) * 6 + i2 + 1] += wv * r1 * r2;
        }
        for (int ky = 0; ky < 5; ky++)
            for (int kx = 0; kx < 5; kx++)
                g_K2[(ci * 64 + co) * 25 + ky * 5 + kx] = acc[ky * 6 + kx];
    }
}

// ---------------------------------------------------------------------------
// Kernel 1b: repack conv2 + conv1 weights into per-fragment tf32 layouts.
// Fragment map (validated): k = ks*8 + (lane&3) + 4h, n = nt*8 + (lane>>2)
// ---------------------------------------------------------------------------
__global__ void repack_w_k() {
    int idx = blockIdx.x * 256 + threadIdx.x;
    if (idx < 25 * 2048) {
        int tap = idx / 2048, r = idx % 2048;
        int ks = r >> 9;
        int r2 = r & 511;
        int nt = r2 >> 6;
        int r3 = r2 & 63;
        int lane = r3 >> 1, h = r3 & 1;
        int k = ks * 8 + (lane & 3) + 4 * h;
        int n = nt * 8 + (lane >> 2);
        g_K2p[idx] = to_tf32(g_K2[(k * 64 + n) * 25 + tap]);
    } else if (idx < 25 * 2048 + 1024) {
        int q = idx - 25 * 2048;
        int ks = q >> 8;
        int nt = (q >> 6) & 3;
        int r3 = q & 63;
        int lane = r3 >> 1, h = r3 & 1;
        int k = ks * 8 + (lane & 3) + 4 * h;   // tap index (25..31 pad)
        int n = nt * 8 + (lane >> 2);          // co
        g_K1p[q] = (k < 25) ? to_tf32(g_K1[n * 25 + k]) : 0.f;
    }
}

// ---------------------------------------------------------------------------
// Kernel 2: pack fc1_w into fragment-ordered tf32 layout.
// ---------------------------------------------------------------------------
__global__ void pack_fc1w_k(const float* __restrict__ w) {
    int idx = blockIdx.x * 256 + threadIdx.x;
    if (idx >= 392 * 1024) return;
    int ks = idx >> 10;
    int r  = idx & 1023;
    int nt = r >> 6;
    int r2 = r & 63;
    int lane = r2 >> 1, h = r2 & 1;
    int k = ks * 8 + (lane & 3) + 4 * h;
    int n = nt * 8 + (lane >> 2);
    int pos = k >> 6, co = k & 63;
    g_fc1wp[idx] = to_tf32(w[n * 3136 + co * 49 + pos]);
}

// ---------------------------------------------------------------------------
// Kernel 3: FUSED conv1+conv2, all tensor-core, per image.
// Phase 1: conv1 implicit GEMM from the 32x32 padded image in smem,
//   7 groups of 8 m-tiles (4 image rows each), pool+bias+relu into the
//   smem-resident padded [pos][ci] buffer (tf32). Staging uses the (still
//   unused) conv2 weight-buffer region.
// Phase 2: R10-proven conv2 implicit GEMM over 25 taps reading that smem
//   buffer directly (input cp.async eliminated), pooled epilogue -> g_pool2.
// smem: 1056 + 12096 + 10240 = 23392 floats = 93.6 KB -> 2 CTAs/SM.
// ---------------------------------------------------------------------------
#define FU_THREADS 256
#define FU_XS 1056
#define FU_BCHUNK 10240                       // 5 taps of packed conv2 B
#define FU_SMEM_FL (FU_XS + P1FL + FU_BCHUNK) // 23392
#define C1_STAG_STRIDE 34
#define C2_STAG_STRIDE 66                     // conv2 C staging: 256*66=16896<=23392

__global__ __launch_bounds__(FU_THREADS, 2) void conv12_k(const float* __restrict__ x,
                                                          const float* __restrict__ b1,
                                                          const float* __restrict__ b2) {
    extern __shared__ float sm[];
    float* xs     = sm;                 // padded 32x32 image (+ zero tail)
    float* in_lin = sm + FU_XS;         // [336][36] conv1 output, tf32
    float* bbuf   = sm + FU_XS + P1FL;  // conv2 weight chunk / conv1 staging

    int b = blockIdx.x;
    int t = threadIdx.x;
    int warp = t >> 5, lane = t & 31;
    int g = lane >> 2, tig = lane & 3;

    // ---- load image, zero in_lin ----
    const float* xp = x + b * 784;
    for (int i = t; i < FU_XS; i += FU_THREADS) {
        float v = 0.f;
        if (i < 1024) {
            int r = (i >> 5) - 2, c = (i & 31) - 2;
            if (r >= 0 && r < 28 && c >= 0 && c < 28) v = xp[r * 28 + c];
        }
        xs[i] = v;
    }
    for (int i = t; i < P1FL; i += FU_THREADS) in_lin[i] = 0.f;

    // conv1 B fragments -> registers; per-thread tap-shift table; bias
    float2 bf[4][4];
#pragma unroll
    for (int ks = 0; ks < 4; ks++)
#pragma unroll
        for (int nt = 0; nt < 4; nt++)
            bf[ks][nt] = *(const float2*)(g_K1p + ((ks * 4 + nt) * 32 + lane) * 2);
    int sh[4][2];
#pragma unroll
    for (int ks = 0; ks < 4; ks++)
#pragma unroll
        for (int h = 0; h < 2; h++) {
            int k = ks * 8 + tig + 4 * h;
            sh[ks][h] = (k < 25) ? (k / 5) * 32 + (k % 5) : 0;
        }
    float b1v = b1[lane];

    __syncthreads();

    // ---- Phase 1: conv1. 7 groups x (8 m-tiles = 4 image rows) ----
    float* stag1 = bbuf;                // [128][34] = 4352 floats
#pragma unroll 1
    for (int gi = 0; gi < 7; gi++) {
        int m0 = gi * 128 + warp * 16 + g;
        float c1[4][4];
#pragma unroll
        for (int i = 0; i < 4; i++)
#pragma unroll
            for (int j = 0; j < 4; j++) c1[i][j] = 0.f;

#pragma unroll
        for (int ks = 0; ks < 4; ks++) {
            unsigned a0 = __float_as_uint(xs[m0 + sh[ks][0]]);
            unsigned a1 = __float_as_uint(xs[m0 + 8 + sh[ks][0]]);
            unsigned a2 = __float_as_uint(xs[m0 + sh[ks][1]]);
            unsigned a3 = __float_as_uint(xs[m0 + 8 + sh[ks][1]]);
#pragma unroll
            for (int nt = 0; nt < 4; nt++)
                mma8(c1[nt], a0, a1, a2, a3,
                     __float_as_uint(bf[ks][nt].x), __float_as_uint(bf[ks][nt].y));
        }
#pragma unroll
        for (int nt = 0; nt < 4; nt++) {
            float* s = stag1 + (warp * 16 + g) * C1_STAG_STRIDE + nt * 8 + 2 * tig;
            *(float2*)s = make_float2(c1[nt][0], c1[nt][1]);
            *(float2*)(s + 8 * C1_STAG_STRIDE) = make_float2(c1[nt][2], c1[nt][3]);
        }
        __syncthreads();

        // pool this group's 2 pooled rows (2 x 14 x 32 cells) into in_lin
        for (int o = t; o < 896; o += FU_THREADS) {
            int ci = o & 31, pq = o >> 5;        // ci == lane
            int pl = pq / 14, xq = pq % 14;
            int lm = (2 * pl) * 32 + 2 * xq;
            float v0 = stag1[lm * C1_STAG_STRIDE + ci];
            float v1 = stag1[(lm + 1) * C1_STAG_STRIDE + ci];
            float v2 = stag1[(lm + 32) * C1_STAG_STRIDE + ci];
            float v3 = stag1[(lm + 33) * C1_STAG_STRIDE + ci];
            float mx = fmaxf(fmaxf(v0, v1), fmaxf(v2, v3)) + b1v;
            int pos = (2 * gi + pl + 2) * 18 + (xq + 2);
            in_lin[pos * P1STRIDE + ci] = to_tf32(fmaxf(mx, 0.f));
        }
        __syncthreads();
    }

    // ---- Phase 2: conv2. Prefetch weight chunk 0, then R10 mainloop ----
    unsigned b_a = smem_u32(bbuf);
    {
        const char* w0 = (const char*)g_K2p;
        for (int i = t; i < FU_BCHUNK / 4; i += FU_THREADS)
            cpa16(b_a + i * 16, w0 + i * 16);
    }
    CP_COMMIT();

    float c[16][4];
#pragma unroll
    for (int i = 0; i < 16; i++)
#pragma unroll
        for (int j = 0; j < 4; j++) c[i][j] = 0.f;

    for (int ch = 0; ch < 5; ch++) {           // ch == ky (5 taps per chunk)
        CP_WAIT0();
        __syncthreads();

#pragma unroll 1
        for (int t5 = 0; t5 < 5; t5++) {       // kx
            int shift = ch * 18 + t5;          // ky*18 + kx
            const float* bt = bbuf + t5 * 2048;
            const unsigned* au =
                (const unsigned*)(in_lin + (warp * 32 + g + shift) * P1STRIDE + tig);

#pragma unroll
            for (int ksI = 0; ksI < 4; ksI++) {
                int kb = ksI * 8;
                unsigned a00 = au[kb],                 a01 = au[8 * P1STRIDE + kb];
                unsigned a02 = au[kb + 4],             a03 = au[8 * P1STRIDE + kb + 4];
                unsigned a10 = au[16 * P1STRIDE + kb], a11 = au[24 * P1STRIDE + kb];
                unsigned a12 = au[16 * P1STRIDE + kb + 4], a13 = au[24 * P1STRIDE + kb + 4];

                const float* bks = bt + ksI * 512 + lane * 2;
#pragma unroll
                for (int nt = 0; nt < 8; nt++) {
                    float2 bv = *(const float2*)(bks + nt * 64);
                    unsigned b0 = __float_as_uint(bv.x);
                    unsigned b1_ = __float_as_uint(bv.y);
                    mma8(c[nt],     a00, a01, a02, a03, b0, b1_);
                    mma8(c[8 + nt], a10, a11, a12, a13, b0, b1_);
                }
            }
        }
        __syncthreads();                       // chunk consumed
        if (ch + 1 < 5) {
            const char* wn = (const char*)(g_K2p + (ch + 1) * FU_BCHUNK);
            for (int i = t; i < FU_BCHUNK / 4; i += FU_THREADS)
                cpa16(b_a + i * 16, wn + i * 16);
            CP_COMMIT();
        }
    }

    // ---- conv2 epilogue: stage C over (now dead) smem, pool, store ----
    float* stag = sm;                          // [m(0..255)][co] stride 66

#pragma unroll
    for (int mt = 0; mt < 2; mt++) {
#pragma unroll
        for (int nt = 0; nt < 8; nt++) {
            float* s = stag + (warp * 32 + mt * 16 + g) * C2_STAG_STRIDE + nt * 8 + 2 * tig;
            *(float2*)s = make_float2(c[mt * 8 + nt][0], c[mt * 8 + nt][1]);
            *(float2*)(s + 8 * C2_STAG_STRIDE) = make_float2(c[mt * 8 + nt][2], c[mt * 8 + nt][3]);
        }
    }
    __syncthreads();

    for (int o = t; o < 3136; o += FU_THREADS) {
        int pos = o >> 6, co = o & 63;
        int yp = pos / 7, xp = pos % 7;
        int m00 = yp * 36 + xp * 2;            // (2yp)*18 + 2xp
        float v0 = stag[m00 * C2_STAG_STRIDE + co];
        float v1 = stag[(m00 + 1) * C2_STAG_STRIDE + co];
        float v2 = stag[(m00 + 18) * C2_STAG_STRIDE + co];
        float v3 = stag[(m00 + 19) * C2_STAG_STRIDE + co];
        float mx = fmaxf(fmaxf(v0, v1), fmaxf(v2, v3)) + b2[co];
        g_pool2[(size_t)b * 3136 + pos * 64 + co] = to_tf32(fmaxf(mx, 0.f));
    }
}

// ---------------------------------------------------------------------------
// Kernel 5: fc1 as tf32 MMA GEMM, BK=64 (R12-proven).
// ---------------------------------------------------------------------------
#define F1_THREADS 256
#define F1_A_FL (32 * 68)       // 2176 floats per A buffer
#define F1_B_FL 8192            // 8 ksteps x 1024 floats per B buffer
#define F1_SMEM_FL (2 * F1_A_FL + 2 * F1_B_FL)   // 20736 floats = 82944 B

__global__ __launch_bounds__(F1_THREADS, 1) void fc1_mma_k(const float* __restrict__ fc1_b) {
    extern __shared__ float fsm[];
    float* Abuf[2] = { fsm, fsm + F1_A_FL };
    float* Bbuf[2] = { fsm + 2 * F1_A_FL, fsm + 2 * F1_A_FL + F1_B_FL };

    int blk = blockIdx.x;               // 0..127, 32 rows each
    int t = threadIdx.x;
    int warp = t >> 5, lane = t & 31;
    int g = lane >> 2, tig = lane & 3;
    int mw = warp & 1;                  // 0..1
    int nw = warp >> 1;                 // 0..3

    unsigned as_a[2] = { smem_u32(Abuf[0]), smem_u32(Abuf[1]) };
    unsigned bs_a[2] = { smem_u32(Bbuf[0]), smem_u32(Bbuf[1]) };

    const float* Ag = g_pool2 + (size_t)blk * 32 * 3136;

    // chunk 0: A (512 cpa16) + B (2048 cpa16)
#pragma unroll
    for (int l = 0; l < 2; l++) {
        int i = t + l * F1_THREADS;               // 0..511
        int row = i >> 4, q = i & 15;
        cpa16(as_a[0] + (row * 68 + q * 4) * 4, Ag + row * 3136 + q * 4);
    }
    for (int i = t; i < 2048; i += F1_THREADS)
        cpa16(bs_a[0] + i * 16, g_fc1wp + i * 4);
    CP_COMMIT();

    float c[4][4];
#pragma unroll
    for (int i = 0; i < 4; i++)
#pragma unroll
        for (int j = 0; j < 4; j++) c[i][j] = 0.f;

    for (int ch = 0; ch < 49; ch++) {
        if (ch + 1 < 49) {
            int nb = (ch + 1) & 1;
#pragma unroll
            for (int l = 0; l < 2; l++) {
                int i = t + l * F1_THREADS;
                int row = i >> 4, q = i & 15;
                cpa16(as_a[nb] + (row * 68 + q * 4) * 4,
                      Ag + row * 3136 + (ch + 1) * 64 + q * 4);
            }
            const float* bsrc = g_fc1wp + (ch + 1) * F1_B_FL;
            for (int i = t; i < 2048; i += F1_THREADS)
                cpa16(bs_a[nb] + i * 16, bsrc + i * 4);
            CP_COMMIT();
            CP_WAIT1();
        } else {
            CP_WAIT0();
        }
        __syncthreads();

        const float* A_ = Abuf[ch & 1];
        const float* B_ = Bbuf[ch & 1];
#pragma unroll
        for (int ks = 0; ks < 8; ks++) {
            const unsigned* au = (const unsigned*)(A_ + (mw * 16 + g) * 68 + ks * 8 + tig);
            unsigned a0 = au[0], a1 = au[8 * 68], a2 = au[4], a3 = au[8 * 68 + 4];
            const float* bp = B_ + (ks * 16 + nw * 4) * 64 + lane * 2;
#pragma unroll
            for (int nt = 0; nt < 4; nt++) {
                float2 bv = *(const float2*)(bp + nt * 64);
                mma8(c[nt], a0, a1, a2, a3,
                     __float_as_uint(bv.x), __float_as_uint(bv.y));
            }
        }
        __syncthreads();   // buffer reuse safety before next prefetch
    }

    // epilogue: bias + relu, direct store
    int m0 = blk * 32 + mw * 16;
#pragma unroll
    for (int nt = 0; nt < 4; nt++) {
        int col = nw * 32 + nt * 8 + 2 * tig;
        float2 bb = *(const float2*)&fc1_b[col];
        float* o0 = g_fc1o + (m0 + g) * 128 + col;
        float* o1 = g_fc1o + (m0 + g + 8) * 128 + col;
        *(float2*)o0 = make_float2(fmaxf(c[nt][0] + bb.x, 0.f),
                                   fmaxf(c[nt][1] + bb.y, 0.f));
        *(float2*)o1 = make_float2(fmaxf(c[nt][2] + bb.x, 0.f),
                                   fmaxf(c[nt][3] + bb.y, 0.f));
    }
}

// ---------------------------------------------------------------------------
// Kernel 6: fc2  out[4096,10] = fc1o[4096,128] @ fc2_w[10,128]^T + b
// ---------------------------------------------------------------------------
__global__ __launch_bounds__(256) void fc2_k(const float* __restrict__ fc2_w,
                                             const float* __restrict__ fc2_b,
                                             float* __restrict__ out) {
    int idx = blockIdx.x * blockDim.x + threadIdx.x;
    if (idx >= NB * 10) return;
    int m = idx / 10, n = idx % 10;
    const float4* h = (const float4*)(g_fc1o + m * 128);
    const float4* w = (const float4*)(fc2_w + n * 128);
    float s = 0.f;
#pragma unroll
    for (int i = 0; i < 32; i++) {
        float4 a = h[i], bb = w[i];
        s += a.x * bb.x + a.y * bb.y + a.z * bb.z + a.w * bb.w;
    }
    out[idx] = s + fc2_b[n];
}

// ---------------------------------------------------------------------------
// Launch
// ---------------------------------------------------------------------------
extern "C" void kernel_launch(void* const* d_in, const int* in_sizes, int n_in,
                              void* d_out, int out_size) {
    const float* x     = (const float*)d_in[0];
    const float* w1    = (const float*)d_in[1];
    const float* p1    = (const float*)d_in[2];
    const float* b1    = (const float*)d_in[3];
    const float* w2    = (const float*)d_in[4];
    const float* p2    = (const float*)d_in[5];
    const float* b2    = (const float*)d_in[6];
    const float* fc1w  = (const float*)d_in[7];
    const float* fc1b  = (const float*)d_in[8];
    const float* fc2w  = (const float*)d_in[9];
    const float* fc2b  = (const float*)d_in[10];
    float* out = (float*)d_out;

    cudaFuncSetAttribute(conv12_k, cudaFuncAttributeMaxDynamicSharedMemorySize,
                         FU_SMEM_FL * 4);
    cudaFuncSetAttribute(fc1_mma_k, cudaFuncAttributeMaxDynamicSharedMemorySize,
                         F1_SMEM_FL * 4);

    build_kernels_k<<<(32 + 64 * 32 + 127) / 128, 128>>>(w1, p1, w2, p2);
    repack_w_k<<<(25 * 2048 + 1024 + 255) / 256, 256>>>();
    pack_fc1w_k<<<(392 * 1024 + 255) / 256, 256>>>(fc1w);
    conv12_k<<<NB, FU_THREADS, FU_SMEM_FL * 4>>>(x, b1, b2);
    fc1_mma_k<<<NB / 32, F1_THREADS, F1_SMEM_FL * 4>>>(fc1b);
    fc2_k<<<(NB * 10 + 255) / 256, 256>>>(fc2w, fc2b, out);
}